// round 16
// baseline (speedup 1.0000x reference)
#include <cuda_runtime.h>
#include <math.h>

#define NBv 16
#define NLv 64
#define Vv  16384
#define Dv  256
#define TK  16
#define NIT 8
#define NROWS (NBv*NLv)   // 1024

// ---------------- scratch (static device memory; no allocs) ----------------
__device__ float  g_logits[NROWS][TK];
__device__ int    g_topidx[NROWS][TK];
__device__ int    g_map[NROWS];
__device__ float  g_rowsum[NROWS];
__device__ int    g_samples[NIT][NROWS];
__device__ float  g_HW[NBv][NLv*Dv];
__device__ float  g_scores[NIT][NBv];
__device__ int    g_best[NROWS];
__device__ int    g_done;          // zero-init; reset by last block each run

// ---------------- threefry2x32 (JAX 20-round), host+device ----------------
__host__ __device__ inline void tf2x32(unsigned k0, unsigned k1, unsigned& x0, unsigned& x1){
  unsigned ks2 = k0 ^ k1 ^ 0x1BD11BDAu;
#define ROTL32(x,d) (((x)<<(d))|((x)>>(32-(d))))
#define TFRND(r) { x0 += x1; x1 = ROTL32(x1,(r)); x1 ^= x0; }
  x0 += k0; x1 += k1;
  TFRND(13) TFRND(15) TFRND(26) TFRND(6)
  x0 += k1; x1 += ks2 + 1u;
  TFRND(17) TFRND(29) TFRND(16) TFRND(24)
  x0 += ks2; x1 += k0 + 2u;
  TFRND(13) TFRND(15) TFRND(26) TFRND(6)
  x0 += k0; x1 += k1 + 3u;
  TFRND(17) TFRND(29) TFRND(16) TFRND(24)
  x0 += k1; x1 += ks2 + 4u;
  TFRND(13) TFRND(15) TFRND(26) TFRND(6)
  x0 += ks2; x1 += k0 + 5u;
#undef TFRND
#undef ROTL32
}

struct Keys { unsigned a[2*NIT]; };

// ---------------- f32x2 helpers ----------------
__device__ __forceinline__ unsigned long long pk2(float x, float y){
  unsigned long long r; asm("mov.b64 %0, {%1, %2};" : "=l"(r) : "f"(x), "f"(y)); return r;
}
__device__ __forceinline__ unsigned long long fma2(unsigned long long a, unsigned long long b, unsigned long long c){
  unsigned long long d; asm("fma.rn.f32x2 %0, %1, %2, %3;" : "=l"(d) : "l"(a), "l"(b), "l"(c)); return d;
}
__device__ __forceinline__ float2 upk(unsigned long long v){
  float2 f; asm("mov.b64 {%0, %1}, %2;" : "=f"(f.x), "=f"(f.y) : "l"(v)); return f;
}

// ---------------- kernel 1: MERGED topk (blocks 0..1023) + HW GEMM (1024..1087)
__global__ __launch_bounds__(256) void k_pre(const float* __restrict__ probas,
                                             const int* __restrict__ mask,
                                             const float* __restrict__ h_d,
                                             const float* __restrict__ W1){
  int t = threadIdx.x;
  int lane = t & 31, warp = t >> 5;

  if (blockIdx.x >= NROWS){
    // ======== HW[b] = (h_d*mask) @ W1[256:512], 64 blocks ========
    int blk = blockIdx.x - NROWS; int b = blk>>2; int cc = (blk&3)*64;
    int ty=t>>4, tx=t&15;
    __shared__ float As[32][65];
    __shared__ float Bs[32][64];
    __shared__ float mfh[64];
    if (t<64) mfh[t] = (float)mask[b*64+t];
    __syncthreads();
    float acc[4][4];
#pragma unroll
    for (int i=0;i<4;i++)
#pragma unroll
      for (int j=0;j<4;j++) acc[i][j]=0.f;
    for (int k0=0;k0<Dv;k0+=32){
#pragma unroll
      for (int i=0;i<8;i++){
        int e=t+i*256; int r=e>>5, kk=e&31;
        As[kk][r] = h_d[((size_t)b*64+r)*Dv + k0+kk] * mfh[r];
      }
#pragma unroll
      for (int i=0;i<8;i++){
        int e=t+i*256; int kk=e>>6, c=e&63;
        Bs[kk][c] = W1[(size_t)(Dv + k0+kk)*Dv + cc + c];
      }
      __syncthreads();
#pragma unroll
      for (int kk=0;kk<32;kk++){
        float a0=As[kk][ty],a1=As[kk][ty+16],a2=As[kk][ty+32],a3=As[kk][ty+48];
        float w0=Bs[kk][tx],w1=Bs[kk][tx+16],w2=Bs[kk][tx+32],w3=Bs[kk][tx+48];
        acc[0][0]+=a0*w0; acc[0][1]+=a0*w1; acc[0][2]+=a0*w2; acc[0][3]+=a0*w3;
        acc[1][0]+=a1*w0; acc[1][1]+=a1*w1; acc[1][2]+=a1*w2; acc[1][3]+=a1*w3;
        acc[2][0]+=a2*w0; acc[2][1]+=a2*w1; acc[2][2]+=a2*w2; acc[2][3]+=a2*w3;
        acc[3][0]+=a3*w0; acc[3][1]+=a3*w1; acc[3][2]+=a3*w2; acc[3][3]+=a3*w3;
      }
      __syncthreads();
    }
#pragma unroll
    for (int ri=0;ri<4;ri++)
#pragma unroll
      for (int ci=0;ci<4;ci++)
        g_HW[b][(ty+16*ri)*Dv + cc + tx+16*ci] = acc[ri][ci];
    return;
  }

  // ======== per-row top-16 + argmax + logits + rowsum ========
  int row = blockIdx.x;
  const float4* p4 = (const float4*)(probas + (size_t)row * Vv);

  __shared__ unsigned long long cand[512];
  __shared__ int scnt;
  __shared__ float ssum[8];
  __shared__ unsigned long long sw8[8][TK];
  if (t==0) scnt=0;
  __syncthreads();

  const unsigned TH = __float_as_uint(0.997f);
  float sum = 0.f;
#pragma unroll 4
  for (int i=0;i<16;i++){
    int v4 = i*256 + t;
    float4 x = __ldg(&p4[v4]);
    sum += (x.x + x.y) + (x.z + x.w);
    float xs[4] = {x.x, x.y, x.z, x.w};
#pragma unroll
    for (int q=0;q<4;q++){
      unsigned fb = __float_as_uint(xs[q]);
      if (fb > TH){
        int pos = atomicAdd(&scnt, 1);
        if (pos < 512)
          cand[pos] = ((unsigned long long)fb<<32) | (unsigned)(~(v4*4+q));
      }
    }
  }
#pragma unroll
  for (int d=16; d>0; d>>=1) sum += __shfl_xor_sync(0xffffffffu, sum, d);
  if (lane==0) ssum[warp]=sum;
  __syncthreads();
  if (t==0){
    float s2=0.f;
#pragma unroll
    for (int i=0;i<8;i++) s2+=ssum[i];
    g_rowsum[row]=s2;
  }
  int cnt = scnt;

  if (cnt>=16 && cnt<=512){
    if (warp==0){
      int jn = (cnt+31)>>5;
      unsigned long long lm=0ull;
      for (int j=0;j<jn;j++){
        int s=lane+32*j;
        unsigned long long k2 = (s<cnt)? cand[s] : 0ull;
        if (k2>lm) lm=k2;
      }
      unsigned long long mine=0ull;
      for (int r=0;r<TK;r++){
        unsigned long long bk=lm;
#pragma unroll
        for (int d=16;d>0;d>>=1){
          unsigned long long o=__shfl_xor_sync(0xffffffffu,bk,d);
          if (o>bk) bk=o;
        }
        if (lm==bk){       // unique winner (keys distinct)
          lm=0ull;
          for (int j=0;j<jn;j++){
            int s=lane+32*j;
            unsigned long long k2=(s<cnt)? cand[s] : 0ull;
            if (k2==bk) cand[s]=0ull;
            else if (k2>lm) lm=k2;
          }
        }
        if (lane==r) mine=bk;
      }
      if (lane<TK){
        int idx = (int)(~(unsigned)mine);
        float val = __uint_as_float((unsigned)(mine>>32));
        g_topidx[row][lane]=idx;
        g_logits[row][lane] = mask[row] ? logf(val) : 0.0f;
        if (lane==0) g_map[row]=idx;
      }
    }
    return;
  }

  // -------- exact slow fallback (never taken on expected data) --------
  unsigned long long v[TK];
#pragma unroll
  for (int i=0;i<TK;i++) v[i]=0ull;
#pragma unroll 2
  for (int i=0;i<16;i++){
    int v4 = i*256 + t;
    float4 x = __ldg(&p4[v4]);
    float xs[4] = {x.x, x.y, x.z, x.w};
#pragma unroll
    for (int q=0;q<4;q++){
      unsigned fb = __float_as_uint(xs[q]);
      unsigned long long carry = ((unsigned long long)fb<<32) | (unsigned)(~(v4*4+q));
#pragma unroll
      for (int u=0;u<TK;u++){
        unsigned long long hi = (v[u]>carry)? v[u]:carry;
        unsigned long long lo = (v[u]>carry)? carry:v[u];
        v[u]=hi; carry=lo;
      }
    }
  }
  unsigned long long mine = 0ull;
  for (int r=0;r<TK;r++){
    unsigned long long bh = v[0]; int bl = lane;
#pragma unroll
    for (int d=16; d>0; d>>=1){
      unsigned long long oh = __shfl_xor_sync(0xffffffffu, bh, d);
      int ol = __shfl_xor_sync(0xffffffffu, bl, d);
      if (oh > bh){ bh=oh; bl=ol; }
    }
    if (lane==bl){
#pragma unroll
      for (int u=0;u<TK-1;u++) v[u]=v[u+1];
      v[TK-1]=0ull;
    }
    if (lane==r) mine = bh;
  }
  if (lane<TK) sw8[warp][lane] = mine;
  __syncthreads();
  if (warp==0){
    unsigned long long c[4];
    int wsrc = lane>>2, base=(lane&3)*4;
#pragma unroll
    for (int j=0;j<4;j++) c[j]=sw8[wsrc][base+j];
    unsigned long long res = 0ull;
    for (int r=0;r<TK;r++){
      unsigned long long bh=c[0]; int bl=lane;
#pragma unroll
      for (int d=16; d>0; d>>=1){
        unsigned long long oh = __shfl_xor_sync(0xffffffffu, bh, d);
        int ol = __shfl_xor_sync(0xffffffffu, bl, d);
        if (oh > bh){ bh=oh; bl=ol; }
      }
      if (lane==bl){ c[0]=c[1]; c[1]=c[2]; c[2]=c[3]; c[3]=0ull; }
      if (lane==r) res = bh;
    }
    if (lane<TK){
      int idx = (int)(~(unsigned)res);
      float val = __uint_as_float((unsigned)(res>>32));
      g_topidx[row][lane]=idx;
      g_logits[row][lane] = mask[row] ? logf(val) : 0.0f;
      if (lane==0) g_map[row]=idx;
    }
  }
}

// ---------------- kernel 4: FUSED sample -> NE -> Gram -> det -> carry ------
#define NE_STRIDE 260
#define OFF_AS  16640
#define AS_STRIDE 36
#define OFF_BS  (OFF_AS + 64*AS_STRIDE)       // 18944
#define BS_STRIDE 260
#define OFF_M   (OFF_BS + 32*BS_STRIDE)       // 27264
#define OFF_M2  (OFF_M + 64*65)               // 31424
#define SM_FLOATS (OFF_M2 + 64*65)            // 35584
#define M_S(r,c)   sm[OFF_M  + (r)*65 + (c)]
#define M2_S(r,c)  sm[OFF_M2 + (r)*65 + (c)]

__global__ __launch_bounds__(512,1) void k_fused(const float* __restrict__ emb,
                                                 const int* __restrict__ mask,
                                                 const float* __restrict__ W1,
                                                 const float* __restrict__ b1,
                                                 const int* __restrict__ bvocab,
                                                 Keys keys,
                                                 float* __restrict__ out_scores){
  extern __shared__ float sm[];
  int task=blockIdx.x;                 // k*16+b
  int kit=task>>4, b=task&15;
  int t=threadIdx.x; int warp=t>>5, lane=t&31;
  __shared__ int gid[64]; __shared__ float mf[64]; __shared__ int vld[64];
  __shared__ float fct[64];
  __shared__ int sn;
  __shared__ double sdet;
  if (t<64){ int m=mask[b*64+t]; mf[t]=(float)m; vld[t]=m; }
  if (t==0){ sdet=1.0; sn=0; }
  __syncthreads();

  // ---- phase 0: in-block gumbel sampling for this (kit, b) ----
  {
    unsigned kk0=keys.a[2*kit], kk1=keys.a[2*kit+1];
#pragma unroll
    for (int h=0;h<2;h++){
      int flat = t + h*512;           // 0..1023 = rl*16 + j
      int j = flat & 15, rl = flat >> 4;
      int row = b*64 + rl;
      unsigned x0=0u, x1=(unsigned)(row*TK + j);
      tf2x32(kk0,kk1,x0,x1);
      unsigned bits = x0 ^ x1;
      unsigned ub = (bits>>9) | 0x3f800000u;
      float f = __uint_as_float(ub) - 1.0f;
      float u = (f>0.f)? f : 1.17549435e-38f;
      float s = -logf(-logf(u)) + g_logits[row][j];
      int arg = j;
#pragma unroll
      for (int w=1; w<16; w<<=1){
        float os = __shfl_xor_sync(0xffffffffu, s, w);
        int   oa = __shfl_xor_sync(0xffffffffu, arg, w);
        if (os>s || (os==s && oa<arg)){ s=os; arg=oa; }
      }
      if (j==0){
        int smp = g_topidx[row][arg];
        bool oh = vld[rl] && (rl==63 || !vld[rl+1]);   // l == sLens-1
        if (oh) smp = g_map[row];
        g_samples[kit][row]=smp;
        gid[rl]=bvocab[smp];
      }
    }
  }
  if (t<64 && vld[t] && (t==63 || !vld[t+1])) sn=t+1;   // sLen (prefix mask)
  __syncthreads();

  // ---- phase 1: NE = relu(E@W1[0:256] + HW + b1), 64x256 into smem ----
  unsigned long long acc[4][4];
#pragma unroll
  for (int i=0;i<4;i++)
#pragma unroll
    for (int j=0;j<4;j++) acc[i][j]=0ull;

  float4 pa; float4 pb[4];
  { int r=t>>3, kq=t&7;
    float4 v=*(const float4*)&emb[(size_t)gid[r]*Dv + 4*kq];
    float m=mf[r]; v.x*=m; v.y*=m; v.z*=m; v.w*=m; pa=v; }
#pragma unroll
  for (int i=0;i<4;i++){ int e=t+i*512; int kk=e>>6, cq=e&63;
    pb[i]=*(const float4*)&W1[(size_t)kk*Dv + 4*cq]; }

  for (int tile=0;tile<8;tile++){
    { int r=t>>3, kq=t&7;
      *(float4*)&sm[OFF_AS + r*AS_STRIDE + 4*kq] = pa; }
#pragma unroll
    for (int i=0;i<4;i++){ int e=t+i*512; int kk=e>>6, cq=e&63;
      *(float4*)&sm[OFF_BS + kk*BS_STRIDE + 4*cq] = pb[i]; }
    __syncthreads();
    if (tile<7){
      int k0=32*(tile+1);
      { int r=t>>3, kq=t&7;
        float4 v=*(const float4*)&emb[(size_t)gid[r]*Dv + k0 + 4*kq];
        float m=mf[r]; v.x*=m; v.y*=m; v.z*=m; v.w*=m; pa=v; }
#pragma unroll
      for (int i=0;i<4;i++){ int e=t+i*512; int kk=e>>6, cq=e&63;
        pb[i]=*(const float4*)&W1[(size_t)(k0+kk)*Dv + 4*cq]; }
    }
#pragma unroll
    for (int kq=0;kq<8;kq++){
      float4 aq[4];
#pragma unroll
      for (int ri=0;ri<4;ri++)
        aq[ri]=*(const float4*)&sm[OFF_AS + (warp+16*ri)*AS_STRIDE + 4*kq];
#pragma unroll
      for (int s=0;s<4;s++){
        ulonglong2 u0=*(const ulonglong2*)&sm[OFF_BS + (4*kq+s)*BS_STRIDE + 4*lane];
        ulonglong2 u1=*(const ulonglong2*)&sm[OFF_BS + (4*kq+s)*BS_STRIDE + 4*lane+128];
        unsigned long long wp0=u0.x, wp1=u0.y, wp2=u1.x, wp3=u1.y;
#pragma unroll
        for (int ri=0;ri<4;ri++){
          float av = (s==0)?aq[ri].x:(s==1)?aq[ri].y:(s==2)?aq[ri].z:aq[ri].w;
          unsigned long long ap=pk2(av,av);
          acc[ri][0]=fma2(ap,wp0,acc[ri][0]);
          acc[ri][1]=fma2(ap,wp1,acc[ri][1]);
          acc[ri][2]=fma2(ap,wp2,acc[ri][2]);
          acc[ri][3]=fma2(ap,wp3,acc[ri][3]);
        }
      }
    }
    __syncthreads();
  }
#pragma unroll
  for (int ri=0;ri<4;ri++){
    int r=warp+16*ri;
#pragma unroll
    for (int p=0;p<2;p++){
      float2 v0=upk(acc[ri][2*p]), v1=upk(acc[ri][2*p+1]);
      int c=4*lane+128*p;
      float4 hw=*(const float4*)&g_HW[b][r*Dv+c];
      float4 bb=*(const float4*)&b1[c];
      float4 o;
      o.x=fmaxf(v0.x+hw.x+bb.x,0.f);
      o.y=fmaxf(v0.y+hw.y+bb.y,0.f);
      o.z=fmaxf(v1.x+hw.z+bb.z,0.f);
      o.w=fmaxf(v1.y+hw.w+bb.w,0.f);
      *(float4*)&sm[r*NE_STRIDE+c]=o;
    }
  }
  __syncthreads();

  // ---- phase 2: Gram, k-split over thread halves, then merged+masked ----
  {
    int half = t>>8;            // 0: k<128, 1: k>=128
    int tt = t&255;
    int ti=tt>>4, tj=tt&15;
    unsigned long long g2[4][4];
#pragma unroll
    for (int i=0;i<4;i++)
#pragma unroll
      for (int j=0;j<4;j++) g2[i][j]=0ull;
    int q0 = 32*half;
#pragma unroll 4
    for (int qq=0;qq<32;qq++){
      int q = q0+qq;
      unsigned long long alo[4],ahi[4],clo[4],chi[4];
#pragma unroll
      for (int m=0;m<4;m++){
        ulonglong2 ua=*(const ulonglong2*)&sm[(ti+16*m)*NE_STRIDE+4*q];
        ulonglong2 uc=*(const ulonglong2*)&sm[(tj+16*m)*NE_STRIDE+4*q];
        alo[m]=ua.x; ahi[m]=ua.y;
        clo[m]=uc.x; chi[m]=uc.y;
      }
#pragma unroll
      for (int i=0;i<4;i++)
#pragma unroll
        for (int j=0;j<4;j++){
          g2[i][j]=fma2(alo[i],clo[j],g2[i][j]);
          g2[i][j]=fma2(ahi[i],chi[j],g2[i][j]);
        }
    }
#pragma unroll
    for (int i=0;i<4;i++)
#pragma unroll
      for (int j=0;j<4;j++){
        int r=ti+16*i, c=tj+16*j;
        float2 gv=upk(g2[i][j]);
        float v=gv.x+gv.y;
        if (half==0) M_S(r,c)=v; else M2_S(r,c)=v;
      }
    __syncthreads();
    if (t<256){
#pragma unroll
      for (int i=0;i<4;i++)
#pragma unroll
        for (int j=0;j<4;j++){
          int r=ti+16*i, c=tj+16*j;
          float v = M_S(r,c) + M2_S(r,c);
          if (!(vld[r] && vld[c])) v=(r==c)?1.f:0.f;
          M_S(r,c)=v;
        }
    }
    __syncthreads();
  }

  // ---- phase 3: no-pivot LU det over leading sLen block ----
  int sl = sn;
  for (int i=0;i<sl;i++){
    float piv = M_S(i,i);
    if (t<64 && t>i) fct[t]=M_S(t,i)/piv;
    if (t==0) sdet *= (double)piv;
    __syncthreads();
    int tr=t>>6, tc=t&63;
    if (tc>i){
      float mi=M_S(i,tc);
      for (int r=i+1+tr; r<sl; r+=8)
        M_S(r,tc) -= fct[r]*mi;
    }
    __syncthreads();
  }
  if (t==0) g_scores[kit][b] = (float)sdet;

  // ---- phase 4: last finishing block performs the scan-carry ----
  __threadfence();
  __syncthreads();
  __shared__ int s_last;
  if (t==0) s_last = (atomicAdd(&g_done,1)==127);
  __syncthreads();
  if (!s_last) return;

  __shared__ float ms[NBv];
  __shared__ int imp[NBv];
  __shared__ int s_ost, s_count, s_stop;
  if (t<NBv) ms[t]=-INFINITY;
  int best0 = g_map[t], best1 = g_map[t+512];
  if (t==0){s_count=0;s_stop=0;s_ost=0;}
  __syncthreads();
  for (int k=0;k<NIT;k++){
    if (t<NBv) imp[t] = (g_scores[k][t] > ms[t])?1:0;
    __syncthreads();
    if (t==0){
      int a=0;
      for (int bb=0;bb<NBv;bb++) a|=imp[bb];
      s_ost = s_stop;                      // upd uses OLD stopped
      s_count = a?0:(s_count+1);
      if ((!a) && s_count>=2) s_stop=1;
    }
    __syncthreads();
    if (t<NBv && imp[t] && !s_ost) ms[t]=g_scores[k][t];
    if (imp[t>>6] && !s_ost)       best0=g_samples[k][t];
    if (imp[(t>>6)+8] && !s_ost)   best1=g_samples[k][t+512];
    __syncthreads();
  }
  g_best[t]=best0; g_best[t+512]=best1;
  if (t<NBv) out_scores[t]=ms[t];
  if (t==0) g_done=0;                      // reset for next graph replay
}

// ---------------- kernel 7: diverse_proba scatter-renormalize (1 pass) ------
__global__ __launch_bounds__(256) void k_out(const float* __restrict__ probas,
                                             const int* __restrict__ mask,
                                             float* __restrict__ out){
  int row=blockIdx.x;
  const float4* p4 = (const float4*)(probas + (size_t)row*Vv);
  float4* o4 = (float4*)(out + (size_t)row*Vv);
  int t=threadIdx.x;
  int bv = g_best[row];
  int bv4 = bv>>2, bvl = bv&3;
  float nm;
  if (mask[row]){
    float pbst = __ldg(&probas[(size_t)row*Vv + bv]);
    nm = 0.2f*g_rowsum[row] + 0.6f*pbst;
  } else nm = 1e-10f;
  float inv = 1.0f/nm;
#pragma unroll 4
  for (int i=0;i<16;i++){
    int v4=i*256+t;
    float4 x = __ldg(&p4[v4]);
    float w0=(v4==bv4&&bvl==0)?0.8f:0.2f, w1=(v4==bv4&&bvl==1)?0.8f:0.2f;
    float w2=(v4==bv4&&bvl==2)?0.8f:0.2f, w3=(v4==bv4&&bvl==3)?0.8f:0.2f;
    float4 y; y.x=x.x*w0*inv; y.y=x.y*w1*inv; y.z=x.z*w2*inv; y.w=x.w*w3*inv;
    __stcs(&o4[v4], y);
  }
}

// ---------------- launch ----------------
extern "C" void kernel_launch(void* const* d_in, const int* in_sizes, int n_in,
                              void* d_out, int out_size){
  const float* probas = (const float*)d_in[0];
  const float* h_d    = (const float*)d_in[1];
  const int*   mask   = (const int*)d_in[2];
  const int*   bvocab = (const int*)d_in[3];
  const float* emb    = (const float*)d_in[4];
  const float* W1     = (const float*)d_in[5];
  const float* b1     = (const float*)d_in[6];
  float* out = (float*)d_out;
  (void)in_sizes; (void)n_in;

  Keys keys;
  for (int k=0;k<NIT;k++){
    unsigned x0=0u, x1=(unsigned)k;
    tf2x32(0u,42u,x0,x1);
    keys.a[2*k]=x0; keys.a[2*k+1]=x1;
  }

  const int smemBytes = SM_FLOATS * 4;   // 142,336 B
  cudaFuncSetAttribute(k_fused, cudaFuncAttributeMaxDynamicSharedMemorySize, smemBytes);

  k_pre   <<<NROWS+64,256>>>(probas, mask, h_d, W1);
  k_fused <<<128,  512, smemBytes>>>(emb, mask, W1, b1, bvocab, keys,
                                     out + (size_t)out_size - NBv);
  k_out   <<<NROWS,256>>>(probas, mask, out);
}

// round 17
// speedup vs baseline: 1.1946x; 1.1946x over previous
#include <cuda_runtime.h>
#include <math.h>

#define NBv 16
#define NLv 64
#define Vv  16384
#define Dv  256
#define TK  16
#define NIT 8
#define NROWS (NBv*NLv)   // 1024

// ---------------- scratch (static device memory; no allocs) ----------------
__device__ float  g_logits[NROWS][TK];
__device__ int    g_topidx[NROWS][TK];
__device__ int    g_map[NROWS];
__device__ float  g_rowsum[NROWS];
__device__ int    g_samples[NIT][NROWS];
__device__ float  g_HW[NBv][NLv*Dv];
__device__ float  g_scores[NIT][NBv];
__device__ int    g_best[NROWS];
__device__ int    g_done;          // zero-init; reset by last block each run

// ---------------- threefry2x32 (JAX 20-round), host+device ----------------
__host__ __device__ inline void tf2x32(unsigned k0, unsigned k1, unsigned& x0, unsigned& x1){
  unsigned ks2 = k0 ^ k1 ^ 0x1BD11BDAu;
#define ROTL32(x,d) (((x)<<(d))|((x)>>(32-(d))))
#define TFRND(r) { x0 += x1; x1 = ROTL32(x1,(r)); x1 ^= x0; }
  x0 += k0; x1 += k1;
  TFRND(13) TFRND(15) TFRND(26) TFRND(6)
  x0 += k1; x1 += ks2 + 1u;
  TFRND(17) TFRND(29) TFRND(16) TFRND(24)
  x0 += ks2; x1 += k0 + 2u;
  TFRND(13) TFRND(15) TFRND(26) TFRND(6)
  x0 += k0; x1 += k1 + 3u;
  TFRND(17) TFRND(29) TFRND(16) TFRND(24)
  x0 += k1; x1 += ks2 + 4u;
  TFRND(13) TFRND(15) TFRND(26) TFRND(6)
  x0 += ks2; x1 += k0 + 5u;
#undef TFRND
#undef ROTL32
}

struct Keys { unsigned a[2*NIT]; };

// ---------------- f32x2 helpers ----------------
__device__ __forceinline__ unsigned long long pk2(float x, float y){
  unsigned long long r; asm("mov.b64 %0, {%1, %2};" : "=l"(r) : "f"(x), "f"(y)); return r;
}
__device__ __forceinline__ unsigned long long fma2(unsigned long long a, unsigned long long b, unsigned long long c){
  unsigned long long d; asm("fma.rn.f32x2 %0, %1, %2, %3;" : "=l"(d) : "l"(a), "l"(b), "l"(c)); return d;
}
__device__ __forceinline__ float2 upk(unsigned long long v){
  float2 f; asm("mov.b64 {%0, %1}, %2;" : "=f"(f.x), "=f"(f.y) : "l"(v)); return f;
}

// ---------------- kernel 1: MERGED HW GEMM (blocks 0..63) + topk (64..1087) -
__global__ __launch_bounds__(256) void k_pre(const float* __restrict__ probas,
                                             const int* __restrict__ mask,
                                             const float* __restrict__ h_d,
                                             const float* __restrict__ W1){
  int t = threadIdx.x;
  int lane = t & 31, warp = t >> 5;

  if (blockIdx.x < 64){
    // ======== HW[b] = (h_d*mask) @ W1[256:512], 64 blocks (wave 1) ========
    int blk = blockIdx.x; int b = blk>>2; int cc = (blk&3)*64;
    int ty=t>>4, tx=t&15;
    __shared__ float As[32][65];
    __shared__ float Bs[32][64];
    __shared__ float mfh[64];
    if (t<64) mfh[t] = (float)mask[b*64+t];
    __syncthreads();
    float acc[4][4];
#pragma unroll
    for (int i=0;i<4;i++)
#pragma unroll
      for (int j=0;j<4;j++) acc[i][j]=0.f;
    for (int k0=0;k0<Dv;k0+=32){
#pragma unroll
      for (int i=0;i<8;i++){
        int e=t+i*256; int r=e>>5, kk=e&31;
        As[kk][r] = h_d[((size_t)b*64+r)*Dv + k0+kk] * mfh[r];
      }
#pragma unroll
      for (int i=0;i<8;i++){
        int e=t+i*256; int kk=e>>6, c=e&63;
        Bs[kk][c] = W1[(size_t)(Dv + k0+kk)*Dv + cc + c];
      }
      __syncthreads();
#pragma unroll
      for (int kk=0;kk<32;kk++){
        float a0=As[kk][ty],a1=As[kk][ty+16],a2=As[kk][ty+32],a3=As[kk][ty+48];
        float w0=Bs[kk][tx],w1=Bs[kk][tx+16],w2=Bs[kk][tx+32],w3=Bs[kk][tx+48];
        acc[0][0]+=a0*w0; acc[0][1]+=a0*w1; acc[0][2]+=a0*w2; acc[0][3]+=a0*w3;
        acc[1][0]+=a1*w0; acc[1][1]+=a1*w1; acc[1][2]+=a1*w2; acc[1][3]+=a1*w3;
        acc[2][0]+=a2*w0; acc[2][1]+=a2*w1; acc[2][2]+=a2*w2; acc[2][3]+=a2*w3;
        acc[3][0]+=a3*w0; acc[3][1]+=a3*w1; acc[3][2]+=a3*w2; acc[3][3]+=a3*w3;
      }
      __syncthreads();
    }
#pragma unroll
    for (int ri=0;ri<4;ri++)
#pragma unroll
      for (int ci=0;ci<4;ci++)
        g_HW[b][(ty+16*ri)*Dv + cc + tx+16*ci] = acc[ri][ci];
    return;
  }

  // ======== per-row top-16 + argmax + logits + rowsum ========
  int row = blockIdx.x - 64;
  const float4* p4 = (const float4*)(probas + (size_t)row * Vv);

  __shared__ unsigned long long cand[512];
  __shared__ int scnt;
  __shared__ float ssum[8];
  if (t==0) scnt=0;
  __syncthreads();

  const unsigned TH = __float_as_uint(0.997f);
  float sum = 0.f;
#pragma unroll
  for (int h=0;h<2;h++){
    float4 xa[8];
#pragma unroll
    for (int i=0;i<8;i++) xa[i]=__ldg(&p4[(h*8+i)*256+t]);
#pragma unroll
    for (int i=0;i<8;i++){
      int v4 = (h*8+i)*256+t;
      sum += (xa[i].x + xa[i].y) + (xa[i].z + xa[i].w);
      float xs[4] = {xa[i].x, xa[i].y, xa[i].z, xa[i].w};
#pragma unroll
      for (int q=0;q<4;q++){
        unsigned fb = __float_as_uint(xs[q]);
        if (fb > TH){
          int pos = atomicAdd(&scnt, 1);
          if (pos < 512)
            cand[pos] = ((unsigned long long)fb<<32) | (unsigned)(~(v4*4+q));
        }
      }
    }
  }
#pragma unroll
  for (int d=16; d>0; d>>=1) sum += __shfl_xor_sync(0xffffffffu, sum, d);
  if (lane==0) ssum[warp]=sum;
  __syncthreads();
  if (t==0){
    float s2=0.f;
#pragma unroll
    for (int i=0;i<8;i++) s2+=ssum[i];
    g_rowsum[row]=s2;
  }
  int cnt = scnt;
  if (warp) return;

  // warp 0 finishes the row
  int mrow = mask[row];
  if (cnt>=16 && cnt<=512){
    int jn = (cnt+31)>>5;
    unsigned long long lm=0ull;
    for (int j=0;j<jn;j++){
      int s=lane+32*j;
      unsigned long long k2 = (s<cnt)? cand[s] : 0ull;
      if (k2>lm) lm=k2;
    }
    unsigned long long mine=0ull;
    for (int r=0;r<TK;r++){
      unsigned long long bk=lm;
#pragma unroll
      for (int d=16;d>0;d>>=1){
        unsigned long long o=__shfl_xor_sync(0xffffffffu,bk,d);
        if (o>bk) bk=o;
      }
      if (lm==bk){       // unique winner (keys distinct)
        lm=0ull;
        for (int j=0;j<jn;j++){
          int s=lane+32*j;
          unsigned long long k2=(s<cnt)? cand[s] : 0ull;
          if (k2==bk) cand[s]=0ull;
          else if (k2>lm) lm=k2;
        }
      }
      if (lane==r) mine=bk;
    }
    if (lane<TK){
      int idx = (int)(~(unsigned)mine);
      float val = __uint_as_float((unsigned)(mine>>32));
      g_topidx[row][lane]=idx;
      g_logits[row][lane] = mrow ? logf(val) : 0.0f;
      if (lane==0) g_map[row]=idx;
    }
    return;
  }

  // ---- lean exact fallback: warp-0 global rescan tournament (never taken
  //      on expected data; exact for any input, minimal register cost) ----
  {
    const float* pr = probas + (size_t)row * Vv;
    unsigned long long prev = ~0ull;
    unsigned long long mine = 0ull;
    for (int r=0;r<TK;r++){
      unsigned long long best=0ull;
      for (int v=lane; v<Vv; v+=32){
        unsigned fb = __float_as_uint(__ldg(&pr[v]));
        unsigned long long key = ((unsigned long long)fb<<32) | (unsigned)(~v);
        if (key<prev && key>best) best=key;
      }
#pragma unroll
      for (int d=16;d>0;d>>=1){
        unsigned long long o=__shfl_xor_sync(0xffffffffu,best,d);
        if (o>best) best=o;
      }
      prev = best;
      if (lane==r) mine = best;
    }
    if (lane<TK){
      int idx = (int)(~(unsigned)mine);
      float val = __uint_as_float((unsigned)(mine>>32));
      g_topidx[row][lane]=idx;
      g_logits[row][lane] = mrow ? logf(val) : 0.0f;
      if (lane==0) g_map[row]=idx;
    }
  }
}

// ---------------- kernel 4: FUSED sample -> NE -> Gram -> det -> carry ------
#define NE_STRIDE 260
#define OFF_AS  16640
#define AS_STRIDE 36
#define OFF_BS  (OFF_AS + 64*AS_STRIDE)       // 18944
#define BS_STRIDE 260
#define OFF_M   (OFF_BS + 32*BS_STRIDE)       // 27264
#define OFF_M2  (OFF_M + 64*65)               // 31424
#define SM_FLOATS (OFF_M2 + 64*65)            // 35584
#define M_S(r,c)   sm[OFF_M  + (r)*65 + (c)]
#define M2_S(r,c)  sm[OFF_M2 + (r)*65 + (c)]

__global__ __launch_bounds__(512,1) void k_fused(const float* __restrict__ emb,
                                                 const int* __restrict__ mask,
                                                 const float* __restrict__ W1,
                                                 const float* __restrict__ b1,
                                                 const int* __restrict__ bvocab,
                                                 Keys keys,
                                                 float* __restrict__ out_scores){
  extern __shared__ float sm[];
  int task=blockIdx.x;                 // k*16+b
  int kit=task>>4, b=task&15;
  int t=threadIdx.x; int warp=t>>5, lane=t&31;
  __shared__ int gid[64]; __shared__ float mf[64]; __shared__ int vld[64];
  __shared__ float fct[64];
  __shared__ int sn;
  __shared__ double sdet;
  if (t<64){ int m=mask[b*64+t]; mf[t]=(float)m; vld[t]=m; }
  if (t==0){ sdet=1.0; sn=0; }
  __syncthreads();

  // ---- phase 0: in-block gumbel sampling for this (kit, b) ----
  {
    unsigned kk0=keys.a[2*kit], kk1=keys.a[2*kit+1];
#pragma unroll
    for (int h=0;h<2;h++){
      int flat = t + h*512;           // 0..1023 = rl*16 + j
      int j = flat & 15, rl = flat >> 4;
      int row = b*64 + rl;
      unsigned x0=0u, x1=(unsigned)(row*TK + j);
      tf2x32(kk0,kk1,x0,x1);
      unsigned bits = x0 ^ x1;
      unsigned ub = (bits>>9) | 0x3f800000u;
      float f = __uint_as_float(ub) - 1.0f;
      float u = (f>0.f)? f : 1.17549435e-38f;
      float s = -logf(-logf(u)) + g_logits[row][j];
      int arg = j;
#pragma unroll
      for (int w=1; w<16; w<<=1){
        float os = __shfl_xor_sync(0xffffffffu, s, w);
        int   oa = __shfl_xor_sync(0xffffffffu, arg, w);
        if (os>s || (os==s && oa<arg)){ s=os; arg=oa; }
      }
      if (j==0){
        int smp = g_topidx[row][arg];
        bool oh = vld[rl] && (rl==63 || !vld[rl+1]);   // l == sLens-1
        if (oh) smp = g_map[row];
        g_samples[kit][row]=smp;
        gid[rl]=bvocab[smp];
      }
    }
  }
  if (t<64 && vld[t] && (t==63 || !vld[t+1])) sn=t+1;   // sLen (prefix mask)
  __syncthreads();

  // ---- phase 1: NE = relu(E@W1[0:256] + HW + b1), 64x256 into smem ----
  unsigned long long acc[4][4];
#pragma unroll
  for (int i=0;i<4;i++)
#pragma unroll
    for (int j=0;j<4;j++) acc[i][j]=0ull;

  float4 pa; float4 pb[4];
  { int r=t>>3, kq=t&7;
    float4 v=*(const float4*)&emb[(size_t)gid[r]*Dv + 4*kq];
    float m=mf[r]; v.x*=m; v.y*=m; v.z*=m; v.w*=m; pa=v; }
#pragma unroll
  for (int i=0;i<4;i++){ int e=t+i*512; int kk=e>>6, cq=e&63;
    pb[i]=*(const float4*)&W1[(size_t)kk*Dv + 4*cq]; }

  for (int tile=0;tile<8;tile++){
    { int r=t>>3, kq=t&7;
      *(float4*)&sm[OFF_AS + r*AS_STRIDE + 4*kq] = pa; }
#pragma unroll
    for (int i=0;i<4;i++){ int e=t+i*512; int kk=e>>6, cq=e&63;
      *(float4*)&sm[OFF_BS + kk*BS_STRIDE + 4*cq] = pb[i]; }
    __syncthreads();
    if (tile<7){
      int k0=32*(tile+1);
      { int r=t>>3, kq=t&7;
        float4 v=*(const float4*)&emb[(size_t)gid[r]*Dv + k0 + 4*kq];
        float m=mf[r]; v.x*=m; v.y*=m; v.z*=m; v.w*=m; pa=v; }
#pragma unroll
      for (int i=0;i<4;i++){ int e=t+i*512; int kk=e>>6, cq=e&63;
        pb[i]=*(const float4*)&W1[(size_t)(k0+kk)*Dv + 4*cq]; }
    }
#pragma unroll
    for (int kq=0;kq<8;kq++){
      float4 aq[4];
#pragma unroll
      for (int ri=0;ri<4;ri++)
        aq[ri]=*(const float4*)&sm[OFF_AS + (warp+16*ri)*AS_STRIDE + 4*kq];
#pragma unroll
      for (int s=0;s<4;s++){
        ulonglong2 u0=*(const ulonglong2*)&sm[OFF_BS + (4*kq+s)*BS_STRIDE + 4*lane];
        ulonglong2 u1=*(const ulonglong2*)&sm[OFF_BS + (4*kq+s)*BS_STRIDE + 4*lane+128];
        unsigned long long wp0=u0.x, wp1=u0.y, wp2=u1.x, wp3=u1.y;
#pragma unroll
        for (int ri=0;ri<4;ri++){
          float av = (s==0)?aq[ri].x:(s==1)?aq[ri].y:(s==2)?aq[ri].z:aq[ri].w;
          unsigned long long ap=pk2(av,av);
          acc[ri][0]=fma2(ap,wp0,acc[ri][0]);
          acc[ri][1]=fma2(ap,wp1,acc[ri][1]);
          acc[ri][2]=fma2(ap,wp2,acc[ri][2]);
          acc[ri][3]=fma2(ap,wp3,acc[ri][3]);
        }
      }
    }
    __syncthreads();
  }
#pragma unroll
  for (int ri=0;ri<4;ri++){
    int r=warp+16*ri;
#pragma unroll
    for (int p=0;p<2;p++){
      float2 v0=upk(acc[ri][2*p]), v1=upk(acc[ri][2*p+1]);
      int c=4*lane+128*p;
      float4 hw=*(const float4*)&g_HW[b][r*Dv+c];
      float4 bb=*(const float4*)&b1[c];
      float4 o;
      o.x=fmaxf(v0.x+hw.x+bb.x,0.f);
      o.y=fmaxf(v0.y+hw.y+bb.y,0.f);
      o.z=fmaxf(v1.x+hw.z+bb.z,0.f);
      o.w=fmaxf(v1.y+hw.w+bb.w,0.f);
      *(float4*)&sm[r*NE_STRIDE+c]=o;
    }
  }
  __syncthreads();

  // ---- phase 2: Gram, k-split over thread halves, then merged+masked ----
  {
    int half = t>>8;            // 0: k<128, 1: k>=128
    int tt = t&255;
    int ti=tt>>4, tj=tt&15;
    unsigned long long g2[4][4];
#pragma unroll
    for (int i=0;i<4;i++)
#pragma unroll
      for (int j=0;j<4;j++) g2[i][j]=0ull;
    int q0 = 32*half;
#pragma unroll 4
    for (int qq=0;qq<32;qq++){
      int q = q0+qq;
      unsigned long long alo[4],ahi[4],clo[4],chi[4];
#pragma unroll
      for (int m=0;m<4;m++){
        ulonglong2 ua=*(const ulonglong2*)&sm[(ti+16*m)*NE_STRIDE+4*q];
        ulonglong2 uc=*(const ulonglong2*)&sm[(tj+16*m)*NE_STRIDE+4*q];
        alo[m]=ua.x; ahi[m]=ua.y;
        clo[m]=uc.x; chi[m]=uc.y;
      }
#pragma unroll
      for (int i=0;i<4;i++)
#pragma unroll
        for (int j=0;j<4;j++){
          g2[i][j]=fma2(alo[i],clo[j],g2[i][j]);
          g2[i][j]=fma2(ahi[i],chi[j],g2[i][j]);
        }
    }
#pragma unroll
    for (int i=0;i<4;i++)
#pragma unroll
      for (int j=0;j<4;j++){
        int r=ti+16*i, c=tj+16*j;
        float2 gv=upk(g2[i][j]);
        float v=gv.x+gv.y;
        if (half==0) M_S(r,c)=v; else M2_S(r,c)=v;
      }
    __syncthreads();
    if (t<256){
#pragma unroll
      for (int i=0;i<4;i++)
#pragma unroll
        for (int j=0;j<4;j++){
          int r=ti+16*i, c=tj+16*j;
          float v = M_S(r,c) + M2_S(r,c);
          if (!(vld[r] && vld[c])) v=(r==c)?1.f:0.f;
          M_S(r,c)=v;
        }
    }
    __syncthreads();
  }

  // ---- phase 3: no-pivot LU det over leading sLen block ----
  int sl = sn;
  for (int i=0;i<sl;i++){
    float piv = M_S(i,i);
    if (t<64 && t>i) fct[t]=M_S(t,i)/piv;
    if (t==0) sdet *= (double)piv;
    __syncthreads();
    int tr=t>>6, tc=t&63;
    if (tc>i){
      float mi=M_S(i,tc);
      for (int r=i+1+tr; r<sl; r+=8)
        M_S(r,tc) -= fct[r]*mi;
    }
    __syncthreads();
  }
  if (t==0) g_scores[kit][b] = (float)sdet;

  // ---- phase 4: last finishing block performs the scan-carry ----
  __threadfence();
  __syncthreads();
  __shared__ int s_last;
  if (t==0) s_last = (atomicAdd(&g_done,1)==127);
  __syncthreads();
  if (!s_last) return;

  __shared__ float ms[NBv];
  __shared__ int imp[NBv];
  __shared__ int s_ost, s_count, s_stop;
  if (t<NBv) ms[t]=-INFINITY;
  int best0 = g_map[t], best1 = g_map[t+512];
  if (t==0){s_count=0;s_stop=0;s_ost=0;}
  __syncthreads();
  for (int k=0;k<NIT;k++){
    if (t<NBv) imp[t] = (g_scores[k][t] > ms[t])?1:0;
    __syncthreads();
    if (t==0){
      int a=0;
      for (int bb=0;bb<NBv;bb++) a|=imp[bb];
      s_ost = s_stop;                      // upd uses OLD stopped
      s_count = a?0:(s_count+1);
      if ((!a) && s_count>=2) s_stop=1;
    }
    __syncthreads();
    if (t<NBv && imp[t] && !s_ost) ms[t]=g_scores[k][t];
    if (imp[t>>6] && !s_ost)       best0=g_samples[k][t];
    if (imp[(t>>6)+8] && !s_ost)   best1=g_samples[k][t+512];
    __syncthreads();
  }
  g_best[t]=best0; g_best[t+512]=best1;
  if (t<NBv) out_scores[t]=ms[t];
  if (t==0) g_done=0;                      // reset for next graph replay
}

// ---------------- kernel 7: diverse_proba scatter-renormalize (1 pass) ------
__global__ __launch_bounds__(256) void k_out(const float* __restrict__ probas,
                                             const int* __restrict__ mask,
                                             float* __restrict__ out){
  int row=blockIdx.x;
  const float4* p4 = (const float4*)(probas + (size_t)row*Vv);
  float4* o4 = (float4*)(out + (size_t)row*Vv);
  int t=threadIdx.x;
  int bv = g_best[row];
  int bv4 = bv>>2, bvl = bv&3;
  float nm;
  if (mask[row]){
    float pbst = __ldg(&probas[(size_t)row*Vv + bv]);
    nm = 0.2f*g_rowsum[row] + 0.6f*pbst;
  } else nm = 1e-10f;
  float inv = 1.0f/nm;
#pragma unroll 4
  for (int i=0;i<16;i++){
    int v4=i*256+t;
    float4 x = __ldg(&p4[v4]);
    float w0=(v4==bv4&&bvl==0)?0.8f:0.2f, w1=(v4==bv4&&bvl==1)?0.8f:0.2f;
    float w2=(v4==bv4&&bvl==2)?0.8f:0.2f, w3=(v4==bv4&&bvl==3)?0.8f:0.2f;
    float4 y; y.x=x.x*w0*inv; y.y=x.y*w1*inv; y.z=x.z*w2*inv; y.w=x.w*w3*inv;
    __stcs(&o4[v4], y);
  }
}

// ---------------- launch ----------------
extern "C" void kernel_launch(void* const* d_in, const int* in_sizes, int n_in,
                              void* d_out, int out_size){
  const float* probas = (const float*)d_in[0];
  const float* h_d    = (const float*)d_in[1];
  const int*   mask   = (const int*)d_in[2];
  const int*   bvocab = (const int*)d_in[3];
  const float* emb    = (const float*)d_in[4];
  const float* W1     = (const float*)d_in[5];
  const float* b1     = (const float*)d_in[6];
  float* out = (float*)d_out;
  (void)in_sizes; (void)n_in;

  Keys keys;
  for (int k=0;k<NIT;k++){
    unsigned x0=0u, x1=(unsigned)k;
    tf2x32(0u,42u,x0,x1);
    keys.a[2*k]=x0; keys.a[2*k+1]=x1;
  }

  const int smemBytes = SM_FLOATS * 4;   // 142,336 B
  cudaFuncSetAttribute(k_fused, cudaFuncAttributeMaxDynamicSharedMemorySize, smemBytes);

  k_pre   <<<NROWS+64,256>>>(probas, mask, h_d, W1);
  k_fused <<<128,  512, smemBytes>>>(emb, mask, W1, b1, bvocab, keys,
                                     out + (size_t)out_size - NBv);
  k_out   <<<NROWS,256>>>(probas, mask, out);
}